// round 15
// baseline (speedup 1.0000x reference)
#include <cuda_runtime.h>
#include <cuda_bf16.h>

// Problem constants
#define B_   4
#define TQ_  512
#define TKV_ 4096
#define D_   1024
#define H_   8
#define HD_  128

typedef unsigned long long u64;
typedef unsigned int u32;

// ---- packed fp32x2 helpers (flash kernel) ----
__device__ __forceinline__ u64 splat2(float v) {
    u64 r; asm("mov.b64 %0, {%1, %1};" : "=l"(r) : "f"(v)); return r;
}
__device__ __forceinline__ u64 ffma2(u64 a, u64 b, u64 c) {
    u64 d; asm("fma.rn.f32x2 %0, %1, %2, %3;" : "=l"(d) : "l"(a), "l"(b), "l"(c)); return d;
}
__device__ __forceinline__ u64 fmul2(u64 a, u64 b) {
    u64 d; asm("mul.rn.f32x2 %0, %1, %2;" : "=l"(d) : "l"(a), "l"(b)); return d;
}
__device__ __forceinline__ float2 unpk(u64 v) {
    float2 r; asm("mov.b64 {%0, %1}, %2;" : "=f"(r.x), "=f"(r.y) : "l"(v)); return r;
}

// Scratch (device globals; no allocation allowed)
__device__ float g_Q[(size_t)B_ * TQ_ * D_];
__device__ float g_K[(size_t)B_ * TKV_ * D_];
__device__ float g_V[(size_t)B_ * TKV_ * D_];
__device__ float g_A[(size_t)B_ * TQ_ * D_];
__device__ unsigned char g_M[(size_t)B_ * TQ_ * TKV_];
__device__ int g_mask_mode;   // 0=uint8, 1=int32, 2=float32

// ---------------------------------------------------------------------------
// Mask dtype detection + canonicalization (validated R4/R7/R11).
// ---------------------------------------------------------------------------
__global__ void detect_mask_kernel(const unsigned char* __restrict__ m)
{
    __shared__ int s_weird, s_misal;
    if (threadIdx.x == 0) { s_weird = 0; s_misal = 0; }
    __syncthreads();
    int w = 0, ma = 0;
    for (int i = threadIdx.x * 4; i < 65536; i += 256 * 4) {
        uchar4 v = *(const uchar4*)(m + i);
        if (v.x > 1 || v.y > 1 || v.z > 1 || v.w > 1) w = 1;
        if (v.y | v.z | v.w) ma = 1;
    }
    if (w)  atomicOr(&s_weird, 1);
    if (ma) atomicOr(&s_misal, 1);
    __syncthreads();
    if (threadIdx.x == 0)
        g_mask_mode = s_weird ? 2 : (s_misal ? 0 : 1);
}

__global__ __launch_bounds__(256) void convert_mask_kernel(const void* __restrict__ src)
{
    const size_t i4 = ((size_t)blockIdx.x * blockDim.x + threadIdx.x) * 4;
    const int mode = g_mask_mode;
    uchar4 o;
    if (mode == 0) {
        uchar4 v = *(const uchar4*)((const unsigned char*)src + i4);
        o.x = v.x ? 1 : 0; o.y = v.y ? 1 : 0; o.z = v.z ? 1 : 0; o.w = v.w ? 1 : 0;
    } else if (mode == 1) {
        int4 v = *(const int4*)((const int*)src + i4);
        o.x = v.x ? 1 : 0; o.y = v.y ? 1 : 0; o.z = v.z ? 1 : 0; o.w = v.w ? 1 : 0;
    } else {
        float4 v = *(const float4*)((const float*)src + i4);
        o.x = (v.x != 0.f) ? 1 : 0; o.y = (v.y != 0.f) ? 1 : 0;
        o.z = (v.z != 0.f) ? 1 : 0; o.w = (v.w != 0.f) ? 1 : 0;
    }
    *(uchar4*)(g_M + i4) = o;
}

// ---------------------------------------------------------------------------
// Tensor-core GEMM, bf16 split precision (hh + hl + lh), DOUBLE-BUFFERED.
// Y[M,N] = X[M,K] @ W[K,N] + bias. BM=128, BN=128, BK=32; 256 thr = 8 warps.
// One __syncthreads per ktile: [LDG(t+1) | fragLDS+MMA(buf t) | conv(t+1)->buf t^1].
// Conversion of tile t+1 overlaps other warps' MMA of tile t.
// Dynamic smem: 2 buffers x 4 tiles x 128x40 bf16 = 81920 B.
// ---------------------------------------------------------------------------
#define PITCH 40
#define TILE_SZ (128 * PITCH)          // bf16 elements per tile
#define BUF_SZ  (4 * TILE_SZ)          // Ah/Al/Bh/Bl

__device__ __forceinline__ void split2(float x0, float x1, u32& hi, u32& lo) {
    __nv_bfloat16 h0 = __float2bfloat16_rn(x0);
    __nv_bfloat16 h1 = __float2bfloat16_rn(x1);
    __nv_bfloat16 l0 = __float2bfloat16_rn(x0 - __bfloat162float(h0));
    __nv_bfloat16 l1 = __float2bfloat16_rn(x1 - __bfloat162float(h1));
    hi = ((u32)__bfloat16_as_ushort(h1) << 16) | (u32)__bfloat16_as_ushort(h0);
    lo = ((u32)__bfloat16_as_ushort(l1) << 16) | (u32)__bfloat16_as_ushort(l0);
}

__device__ __forceinline__ void mma16816(float* c, const u32* a, const u32* b) {
    asm volatile(
        "mma.sync.aligned.m16n8k16.row.col.f32.bf16.bf16.f32 "
        "{%0,%1,%2,%3}, {%4,%5,%6,%7}, {%8,%9}, {%0,%1,%2,%3};\n"
        : "+f"(c[0]), "+f"(c[1]), "+f"(c[2]), "+f"(c[3])
        : "r"(a[0]), "r"(a[1]), "r"(a[2]), "r"(a[3]), "r"(b[0]), "r"(b[1]));
}

__global__ __launch_bounds__(256) void gemm_mma_kernel(
    const float* __restrict__ X, const float* __restrict__ W,
    const float* __restrict__ bias, float* __restrict__ Y,
    int M, int N, int K)
{
    extern __shared__ __align__(16) __nv_bfloat16 smem_bf[];

    const int tid  = threadIdx.x;
    const int lane = tid & 31;
    const int warp = tid >> 5;
    const int wm   = warp >> 2;      // 0..1
    const int wn   = warp & 3;       // 0..3
    const int gid  = lane >> 2;      // 0..7
    const int tig  = lane & 3;       // 0..3
    const int m0   = blockIdx.y * 128;
    const int n0   = blockIdx.x * 128;

    // Global-load mappings
    const int am  = tid >> 1;            // 0..127
    const int ak0 = (tid & 1) << 4;      // 0 or 16
    const int bn  = tid & 127;           // 0..127
    const int bk0 = (tid >> 7) << 4;     // 0 or 16

    const float* Xp = X + (size_t)(m0 + am) * K + ak0;

    float acc[4][4][4] = {};
    float4 areg[4];
    float  breg[16];

    // --- conversion+store of prefetched registers into buffer `buf` ---
    auto conv_store = [&](__nv_bfloat16* buf) {
        __nv_bfloat16* Ah = buf;
        __nv_bfloat16* Al = buf + TILE_SZ;
        __nv_bfloat16* Bh = buf + 2 * TILE_SZ;
        __nv_bfloat16* Bl = buf + 3 * TILE_SZ;
        {
            u32 h[8], l[8];
            #pragma unroll
            for (int j = 0; j < 4; j++) {
                split2(areg[j].x, areg[j].y, h[2*j],   l[2*j]);
                split2(areg[j].z, areg[j].w, h[2*j+1], l[2*j+1]);
            }
            uint4* dh = (uint4*)(Ah + am * PITCH + ak0);
            uint4* dl = (uint4*)(Al + am * PITCH + ak0);
            dh[0] = make_uint4(h[0], h[1], h[2], h[3]);
            dh[1] = make_uint4(h[4], h[5], h[6], h[7]);
            dl[0] = make_uint4(l[0], l[1], l[2], l[3]);
            dl[1] = make_uint4(l[4], l[5], l[6], l[7]);
        }
        {
            u32 h[8], l[8];
            #pragma unroll
            for (int j = 0; j < 8; j++)
                split2(breg[2*j], breg[2*j+1], h[j], l[j]);
            uint4* dh = (uint4*)(Bh + bn * PITCH + bk0);
            uint4* dl = (uint4*)(Bl + bn * PITCH + bk0);
            dh[0] = make_uint4(h[0], h[1], h[2], h[3]);
            dh[1] = make_uint4(h[4], h[5], h[6], h[7]);
            dl[0] = make_uint4(l[0], l[1], l[2], l[3]);
            dl[1] = make_uint4(l[4], l[5], l[6], l[7]);
        }
    };

    // Prologue: load + convert ktile 0
    #pragma unroll
    for (int j = 0; j < 4; j++)
        areg[j] = *(const float4*)(Xp + j * 4);
    #pragma unroll
    for (int j = 0; j < 16; j++)
        breg[j] = W[(size_t)(bk0 + j) * N + n0 + bn];
    conv_store(smem_bf);
    __syncthreads();

    const int T = K / 32;
    for (int t = 0; t < T; t++) {
        const int k0 = t * 32;
        __nv_bfloat16* cur = smem_bf + (t & 1) * BUF_SZ;
        __nv_bfloat16* nxt = smem_bf + ((t + 1) & 1) * BUF_SZ;

        // Issue gmem loads for ktile t+1 (land during MMA phase)
        if (t + 1 < T) {
            #pragma unroll
            for (int j = 0; j < 4; j++)
                areg[j] = *(const float4*)(Xp + k0 + 32 + j * 4);
            #pragma unroll
            for (int j = 0; j < 16; j++)
                breg[j] = W[(size_t)(k0 + 32 + bk0 + j) * N + n0 + bn];
        }

        // MMA over current buffer
        const __nv_bfloat16* Ah = cur;
        const __nv_bfloat16* Al = cur + TILE_SZ;
        const __nv_bfloat16* Bh = cur + 2 * TILE_SZ;
        const __nv_bfloat16* Bl = cur + 3 * TILE_SZ;
        #pragma unroll
        for (int ks = 0; ks < 32; ks += 16) {
            u32 bh[4][2], bl[4][2];
            #pragma unroll
            for (int nf = 0; nf < 4; nf++) {
                int n = wn * 32 + nf * 8 + gid;
                bh[nf][0] = *(const u32*)(Bh + n * PITCH + ks + tig * 2);
                bh[nf][1] = *(const u32*)(Bh + n * PITCH + ks + 8 + tig * 2);
                bl[nf][0] = *(const u32*)(Bl + n * PITCH + ks + tig * 2);
                bl[nf][1] = *(const u32*)(Bl + n * PITCH + ks + 8 + tig * 2);
            }
            #pragma unroll
            for (int mf = 0; mf < 4; mf++) {
                int m = wm * 64 + mf * 16 + gid;
                u32 ah[4], al[4];
                ah[0] = *(const u32*)(Ah + m * PITCH + ks + tig * 2);
                ah[1] = *(const u32*)(Ah + (m + 8) * PITCH + ks + tig * 2);
                ah[2] = *(const u32*)(Ah + m * PITCH + ks + 8 + tig * 2);
                ah[3] = *(const u32*)(Ah + (m + 8) * PITCH + ks + 8 + tig * 2);
                al[0] = *(const u32*)(Al + m * PITCH + ks + tig * 2);
                al[1] = *(const u32*)(Al + (m + 8) * PITCH + ks + tig * 2);
                al[2] = *(const u32*)(Al + m * PITCH + ks + 8 + tig * 2);
                al[3] = *(const u32*)(Al + (m + 8) * PITCH + ks + 8 + tig * 2);
                #pragma unroll
                for (int nf = 0; nf < 4; nf++) {
                    mma16816(acc[mf][nf], ah, bh[nf]);   // hi*hi
                    mma16816(acc[mf][nf], ah, bl[nf]);   // hi*lo
                    mma16816(acc[mf][nf], al, bh[nf]);   // lo*hi
                }
            }
        }

        // Convert ktile t+1 into the other buffer (overlaps other warps' MMA)
        if (t + 1 < T)
            conv_store(nxt);
        __syncthreads();
    }

    // Epilogue: bias + store
    #pragma unroll
    for (int mf = 0; mf < 4; mf++) {
        int row = m0 + wm * 64 + mf * 16 + gid;
        #pragma unroll
        for (int nf = 0; nf < 4; nf++) {
            int col = n0 + wn * 32 + nf * 8 + tig * 2;
            float2 bb = *(const float2*)(bias + col);
            float2 v0, v1;
            v0.x = acc[mf][nf][0] + bb.x; v0.y = acc[mf][nf][1] + bb.y;
            v1.x = acc[mf][nf][2] + bb.x; v1.y = acc[mf][nf][3] + bb.y;
            *(float2*)(Y + (size_t)row * N + col) = v0;
            *(float2*)(Y + (size_t)(row + 8) * N + col) = v1;
        }
    }
}

#define GEMM_SMEM_BYTES (2 * BUF_SZ * 2)   // 81920

// ---------------------------------------------------------------------------
// Flash attention, fp32 packed f32x2 (validated R7/R11). Unchanged.
// ---------------------------------------------------------------------------
#define QK_PITCH 130
#define FLASH_SMEM_FLOATS (2 * 64 * QK_PITCH + 64 * 128 + 64 * 65)
#define FLASH_SMEM_BYTES  (FLASH_SMEM_FLOATS * 4)

__global__ __launch_bounds__(256) void flash_kernel(
    const float* __restrict__ Q, const float* __restrict__ Kg,
    const float* __restrict__ Vg, float* __restrict__ A)
{
    extern __shared__ float sm[];
    float* Qs = sm;                                     // [64][130]
    float* Ks = sm + 64 * QK_PITCH;                     // [64][130]
    float* Vs = sm + 2 * 64 * QK_PITCH;                 // [64][128]
    float* Ps = sm + 2 * 64 * QK_PITCH + 64 * 128;      // [64][65]  Ps[col][row]

    const int tid = threadIdx.x;
    const int tx = tid & 15;
    const int ty = tid >> 4;
    const int q0 = blockIdx.x * 64;
    const int h  = blockIdx.y;
    const int b  = blockIdx.z;

    const float SCALE = 0.08838834764831843f;  // 1/sqrt(128)
    const float NEG   = -1e30f;

    const float* Qb = Q  + ((size_t)b * TQ_ + q0) * D_ + h * HD_;
    const float* Kb = Kg + (size_t)b * TKV_ * D_ + h * HD_;
    const float* Vb = Vg + (size_t)b * TKV_ * D_ + h * HD_;
    const unsigned char* Mb = g_M + ((size_t)b * TQ_ + q0) * TKV_;

    #pragma unroll
    for (int r = 0; r < 8; r++) {
        int f = tid + 256 * r;
        int i = f >> 5;
        int d4 = (f & 31) << 2;
        float4 v = *(const float4*)(Qb + (size_t)i * D_ + d4);
        float* q = Qs + i * QK_PITCH + d4;
        q[0] = v.x; q[1] = v.y; q[2] = v.z; q[3] = v.w;
    }

    float m[4], l[4];
    u64 acc2[4][4];
    #pragma unroll
    for (int ii = 0; ii < 4; ii++) {
        m[ii] = -INFINITY;
        l[ii] = 0.0f;
        #pragma unroll
        for (int c = 0; c < 4; c++) acc2[ii][c] = 0ull;
    }

    for (int t = 0; t < TKV_ / 64; t++) {
        const int kv0 = t * 64;
        __syncthreads();

        const float* Kt = Kb + (size_t)kv0 * D_;
        const float* Vt = Vb + (size_t)kv0 * D_;
        #pragma unroll
        for (int r = 0; r < 8; r++) {
            int f = tid + 256 * r;
            int j = f >> 5;
            int d4 = (f & 31) << 2;
            float4 kv = *(const float4*)(Kt + (size_t)j * D_ + d4);
            float* kp = Ks + j * QK_PITCH + d4;
            kp[0] = kv.x; kp[1] = kv.y; kp[2] = kv.z; kp[3] = kv.w;
            float4 vv = *(const float4*)(Vt + (size_t)j * D_ + d4);
            *(float4*)(Vs + j * 128 + d4) = vv;
        }
        __syncthreads();

        u64 s2[4][4] = {};
        const float* qrow = Qs + (ty * 4) * QK_PITCH;
        const float* kcol = Ks + tx * QK_PITCH;
        #pragma unroll 4
        for (int d = 0; d < 128; d += 2) {
            u64 q2[4], k2[4];
            #pragma unroll
            for (int ii = 0; ii < 4; ii++)
                q2[ii] = *(const u64*)&qrow[ii * QK_PITCH + d];
            #pragma unroll
            for (int jj = 0; jj < 4; jj++)
                k2[jj] = *(const u64*)&kcol[jj * 16 * QK_PITCH + d];
            #pragma unroll
            for (int ii = 0; ii < 4; ii++)
                #pragma unroll
                for (int jj = 0; jj < 4; jj++)
                    s2[ii][jj] = ffma2(q2[ii], k2[jj], s2[ii][jj]);
        }

        float s[4][4];
        #pragma unroll
        for (int ii = 0; ii < 4; ii++) {
            const unsigned char* mrow = Mb + (size_t)(ty * 4 + ii) * TKV_ + kv0 + tx;
            #pragma unroll
            for (int jj = 0; jj < 4; jj++) {
                float2 p = unpk(s2[ii][jj]);
                float sv = p.x + p.y;
                s[ii][jj] = mrow[16 * jj] ? sv * SCALE : NEG;
            }
        }

        #pragma unroll
        for (int ii = 0; ii < 4; ii++) {
            float rm = fmaxf(fmaxf(s[ii][0], s[ii][1]), fmaxf(s[ii][2], s[ii][3]));
            #pragma unroll
            for (int o = 1; o < 16; o <<= 1)
                rm = fmaxf(rm, __shfl_xor_sync(0xffffffffu, rm, o));
            float mnew = fmaxf(m[ii], rm);
            float corr = __expf(m[ii] - mnew);
            m[ii] = mnew;
            float rs = 0.0f;
            #pragma unroll
            for (int jj = 0; jj < 4; jj++) {
                float p = __expf(s[ii][jj] - mnew);
                s[ii][jj] = p;
                rs += p;
            }
            #pragma unroll
            for (int o = 1; o < 16; o <<= 1)
                rs += __shfl_xor_sync(0xffffffffu, rs, o);
            l[ii] = l[ii] * corr + rs;
            u64 corr2 = splat2(corr);
            #pragma unroll
            for (int c = 0; c < 4; c++) acc2[ii][c] = fmul2(acc2[ii][c], corr2);
        }

        #pragma unroll
        for (int jj = 0; jj < 4; jj++)
            #pragma unroll
            for (int ii = 0; ii < 4; ii++)
                Ps[(tx + 16 * jj) * 65 + ty * 4 + ii] = s[ii][jj];
        __syncthreads();

        #pragma unroll 4
        for (int j = 0; j < 64; j++) {
            u64 p2[4];
            #pragma unroll
            for (int ii = 0; ii < 4; ii++)
                p2[ii] = splat2(Ps[j * 65 + ty * 4 + ii]);
            ulonglong2 va = *(const ulonglong2*)&Vs[j * 128 + tx * 4];
            ulonglong2 vb = *(const ulonglong2*)&Vs[j * 128 + 64 + tx * 4];
            #pragma unroll
            for (int ii = 0; ii < 4; ii++) {
                acc2[ii][0] = ffma2(p2[ii], va.x, acc2[ii][0]);
                acc2[ii][1] = ffma2(p2[ii], va.y, acc2[ii][1]);
                acc2[ii][2] = ffma2(p2[ii], vb.x, acc2[ii][2]);
                acc2[ii][3] = ffma2(p2[ii], vb.y, acc2[ii][3]);
            }
        }
    }

    #pragma unroll
    for (int ii = 0; ii < 4; ii++) {
        float inv = (m[ii] < -1e29f) ? 0.0f : (1.0f / l[ii]);
        int qi = q0 + ty * 4 + ii;
        float* out = A + ((size_t)b * TQ_ + qi) * D_ + h * HD_ + tx * 4;
        float2 c0 = unpk(acc2[ii][0]);
        float2 c1 = unpk(acc2[ii][1]);
        float2 c2 = unpk(acc2[ii][2]);
        float2 c3 = unpk(acc2[ii][3]);
        float4 o1, o2;
        o1.x = c0.x * inv; o1.y = c0.y * inv; o1.z = c1.x * inv; o1.w = c1.y * inv;
        o2.x = c2.x * inv; o2.y = c2.y * inv; o2.z = c3.x * inv; o2.w = c3.y * inv;
        *(float4*)out = o1;
        *(float4*)(out + 64) = o2;
    }
}

// ---------------------------------------------------------------------------
// Launch
// ---------------------------------------------------------------------------
extern "C" void kernel_launch(void* const* d_in, const int* in_sizes, int n_in,
                              void* d_out, int out_size)
{
    const float* xq   = (const float*)d_in[0];
    const float* xkv  = (const float*)d_in[1];
    const void*  mask = d_in[2];
    const float* Wq = (const float*)d_in[3];
    const float* bq = (const float*)d_in[4];
    const float* Wk = (const float*)d_in[5];
    const float* bk = (const float*)d_in[6];
    const float* Wv = (const float*)d_in[7];
    const float* bv = (const float*)d_in[8];
    const float* Wo = (const float*)d_in[9];
    const float* bo = (const float*)d_in[10];

    float *gQ, *gK, *gV, *gA;
    cudaGetSymbolAddress((void**)&gQ, g_Q);
    cudaGetSymbolAddress((void**)&gK, g_K);
    cudaGetSymbolAddress((void**)&gV, g_V);
    cudaGetSymbolAddress((void**)&gA, g_A);

    const int Mq = B_ * TQ_;    // 2048
    const int Mkv = B_ * TKV_;  // 16384

    // Mask normalization
    detect_mask_kernel<<<1, 256>>>((const unsigned char*)mask);
    convert_mask_kernel<<<(B_ * TQ_ * TKV_) / (256 * 4), 256>>>(mask);

    // Projections on tensor cores (bf16 split precision, double-buffered)
    cudaFuncSetAttribute(gemm_mma_kernel, cudaFuncAttributeMaxDynamicSharedMemorySize,
                         GEMM_SMEM_BYTES);
    gemm_mma_kernel<<<dim3(D_ / 128, Mq / 128), 256, GEMM_SMEM_BYTES>>>(
        xq, Wq, bq, gQ, Mq, D_, D_);
    gemm_mma_kernel<<<dim3(D_ / 128, Mkv / 128), 256, GEMM_SMEM_BYTES>>>(
        xkv, Wk, bk, gK, Mkv, D_, D_);
    gemm_mma_kernel<<<dim3(D_ / 128, Mkv / 128), 256, GEMM_SMEM_BYTES>>>(
        xkv, Wv, bv, gV, Mkv, D_, D_);

    // Attention
    cudaFuncSetAttribute(flash_kernel, cudaFuncAttributeMaxDynamicSharedMemorySize,
                         FLASH_SMEM_BYTES);
    flash_kernel<<<dim3(TQ_ / 64, H_, B_), 256, FLASH_SMEM_BYTES>>>(gQ, gK, gV, gA);

    // Output projection
    gemm_mma_kernel<<<dim3(D_ / 128, Mq / 128), 256, GEMM_SMEM_BYTES>>>(
        gA, Wo, bo, (float*)d_out, Mq, D_, D_);
}

// round 17
// speedup vs baseline: 1.4385x; 1.4385x over previous
#include <cuda_runtime.h>
#include <cuda_bf16.h>

// Problem constants
#define B_   4
#define TQ_  512
#define TKV_ 4096
#define D_   1024
#define H_   8
#define HD_  128

typedef unsigned long long u64;
typedef unsigned int u32;

// Scratch (device globals; no allocation allowed)
__device__ float g_Q[(size_t)B_ * TQ_ * D_];
__device__ float g_K[(size_t)B_ * TKV_ * D_];
__device__ float g_V[(size_t)B_ * TKV_ * D_];
__device__ float g_A[(size_t)B_ * TQ_ * D_];
__device__ unsigned char g_M[(size_t)B_ * TQ_ * TKV_];
__device__ int g_mask_mode;
// bf16 split buffers for flash
__device__ __nv_bfloat16 g_Kbh[(size_t)B_ * TKV_ * D_];
__device__ __nv_bfloat16 g_Kbl[(size_t)B_ * TKV_ * D_];
__device__ __nv_bfloat16 g_Vth[(size_t)B_ * D_ * TKV_];   // [b][hd][kv]
__device__ __nv_bfloat16 g_Vtl[(size_t)B_ * D_ * TKV_];

// ---------------------------------------------------------------------------
// Mask dtype detection + canonicalization (validated R4/R7/R11).
// ---------------------------------------------------------------------------
__global__ void detect_mask_kernel(const unsigned char* __restrict__ m)
{
    __shared__ int s_weird, s_misal;
    if (threadIdx.x == 0) { s_weird = 0; s_misal = 0; }
    __syncthreads();
    int w = 0, ma = 0;
    for (int i = threadIdx.x * 4; i < 65536; i += 256 * 4) {
        uchar4 v = *(const uchar4*)(m + i);
        if (v.x > 1 || v.y > 1 || v.z > 1 || v.w > 1) w = 1;
        if (v.y | v.z | v.w) ma = 1;
    }
    if (w)  atomicOr(&s_weird, 1);
    if (ma) atomicOr(&s_misal, 1);
    __syncthreads();
    if (threadIdx.x == 0)
        g_mask_mode = s_weird ? 2 : (s_misal ? 0 : 1);
}

__global__ __launch_bounds__(256) void convert_mask_kernel(const void* __restrict__ src)
{
    const size_t i4 = ((size_t)blockIdx.x * blockDim.x + threadIdx.x) * 4;
    const int mode = g_mask_mode;
    uchar4 o;
    if (mode == 0) {
        uchar4 v = *(const uchar4*)((const unsigned char*)src + i4);
        o.x = v.x ? 1 : 0; o.y = v.y ? 1 : 0; o.z = v.z ? 1 : 0; o.w = v.w ? 1 : 0;
    } else if (mode == 1) {
        int4 v = *(const int4*)((const int*)src + i4);
        o.x = v.x ? 1 : 0; o.y = v.y ? 1 : 0; o.z = v.z ? 1 : 0; o.w = v.w ? 1 : 0;
    } else {
        float4 v = *(const float4*)((const float*)src + i4);
        o.x = (v.x != 0.f) ? 1 : 0; o.y = (v.y != 0.f) ? 1 : 0;
        o.z = (v.z != 0.f) ? 1 : 0; o.w = (v.w != 0.f) ? 1 : 0;
    }
    *(uchar4*)(g_M + i4) = o;
}

// ---------------------------------------------------------------------------
// Split helpers + mma (fragment maps validated in R11).
// ---------------------------------------------------------------------------
__device__ __forceinline__ void split2(float x0, float x1, u32& hi, u32& lo) {
    __nv_bfloat16 h0 = __float2bfloat16_rn(x0);
    __nv_bfloat16 h1 = __float2bfloat16_rn(x1);
    __nv_bfloat16 l0 = __float2bfloat16_rn(x0 - __bfloat162float(h0));
    __nv_bfloat16 l1 = __float2bfloat16_rn(x1 - __bfloat162float(h1));
    hi = ((u32)__bfloat16_as_ushort(h1) << 16) | (u32)__bfloat16_as_ushort(h0);
    lo = ((u32)__bfloat16_as_ushort(l1) << 16) | (u32)__bfloat16_as_ushort(l0);
}

__device__ __forceinline__ void mma16816(float* c, const u32* a, const u32* b) {
    asm volatile(
        "mma.sync.aligned.m16n8k16.row.col.f32.bf16.bf16.f32 "
        "{%0,%1,%2,%3}, {%4,%5,%6,%7}, {%8,%9}, {%0,%1,%2,%3};\n"
        : "+f"(c[0]), "+f"(c[1]), "+f"(c[2]), "+f"(c[3])
        : "r"(a[0]), "r"(a[1]), "r"(a[2]), "r"(a[3]), "r"(b[0]), "r"(b[1]));
}

// ---------------------------------------------------------------------------
// Prepack: fp32 -> bf16 hi/lo elementwise (for K).
// ---------------------------------------------------------------------------
__global__ __launch_bounds__(256) void pack_split_kernel(
    const float* __restrict__ src, __nv_bfloat16* __restrict__ dh,
    __nv_bfloat16* __restrict__ dl)
{
    const size_t i4 = ((size_t)blockIdx.x * 256 + threadIdx.x) * 4;
    float4 v = *(const float4*)(src + i4);
    u32 h0, l0, h1, l1;
    split2(v.x, v.y, h0, l0);
    split2(v.z, v.w, h1, l1);
    *(uint2*)(dh + i4) = make_uint2(h0, h1);
    *(uint2*)(dl + i4) = make_uint2(l0, l1);
}

// ---------------------------------------------------------------------------
// Prepack: V fp32 [b][kv][hd] -> Vt bf16 hi/lo [b][hd][kv]. 64x64 tiles.
// ---------------------------------------------------------------------------
__global__ __launch_bounds__(256) void transpose_split_kernel(
    const float* __restrict__ V, __nv_bfloat16* __restrict__ Th,
    __nv_bfloat16* __restrict__ Tl)
{
    __shared__ float ts[64][68];
    const int tid = threadIdx.x;
    const int kv0 = blockIdx.x * 64;
    const int hd0 = blockIdx.y * 64;
    const int b   = blockIdx.z;

    #pragma unroll
    for (int r = 0; r < 4; r++) {
        int f = tid + 256 * r;
        int row = f >> 4;             // kv
        int c4  = (f & 15) << 2;      // hd
        *(float4*)&ts[row][c4] =
            *(const float4*)(V + ((size_t)b * TKV_ + kv0 + row) * D_ + hd0 + c4);
    }
    __syncthreads();
    #pragma unroll
    for (int r = 0; r < 4; r++) {
        int f = tid + 256 * r;
        int hd  = f >> 4;             // 0..63
        int kv4 = (f & 15) << 2;      // 0..60
        u32 h0, l0, h1, l1;
        split2(ts[kv4 + 0][hd], ts[kv4 + 1][hd], h0, l0);
        split2(ts[kv4 + 2][hd], ts[kv4 + 3][hd], h1, l1);
        size_t off = ((size_t)b * D_ + hd0 + hd) * TKV_ + kv0 + kv4;
        *(uint2*)(Th + off) = make_uint2(h0, h1);
        *(uint2*)(Tl + off) = make_uint2(l0, l1);
    }
}

// ---------------------------------------------------------------------------
// Tensor-core GEMM, bf16 split (hh+hl+lh), single-buffer (R11, validated 442us).
// ---------------------------------------------------------------------------
#define PITCH 40

__global__ __launch_bounds__(256) void gemm_mma_kernel(
    const float* __restrict__ X, const float* __restrict__ W,
    const float* __restrict__ bias, float* __restrict__ Y,
    int M, int N, int K)
{
    __shared__ __align__(16) __nv_bfloat16 Ah[128][PITCH];
    __shared__ __align__(16) __nv_bfloat16 Al[128][PITCH];
    __shared__ __align__(16) __nv_bfloat16 Bh[128][PITCH];
    __shared__ __align__(16) __nv_bfloat16 Bl[128][PITCH];

    const int tid  = threadIdx.x;
    const int lane = tid & 31;
    const int warp = tid >> 5;
    const int wm   = warp >> 2;
    const int wn   = warp & 3;
    const int gid  = lane >> 2;
    const int tig  = lane & 3;
    const int m0   = blockIdx.y * 128;
    const int n0   = blockIdx.x * 128;

    const int am  = tid >> 1;
    const int ak0 = (tid & 1) << 4;
    const int bn  = tid & 127;
    const int bk0 = (tid >> 7) << 4;

    const float* Xp = X + (size_t)(m0 + am) * K + ak0;

    float acc[4][4][4] = {};
    float4 areg[4];
    float  breg[16];

    #pragma unroll
    for (int j = 0; j < 4; j++)
        areg[j] = *(const float4*)(Xp + j * 4);
    #pragma unroll
    for (int j = 0; j < 16; j++)
        breg[j] = W[(size_t)(bk0 + j) * N + n0 + bn];

    for (int k0 = 0; k0 < K; k0 += 32) {
        __syncthreads();
        {
            u32 h[8], l[8];
            #pragma unroll
            for (int j = 0; j < 4; j++) {
                split2(areg[j].x, areg[j].y, h[2*j],   l[2*j]);
                split2(areg[j].z, areg[j].w, h[2*j+1], l[2*j+1]);
            }
            uint4* dh = (uint4*)&Ah[am][ak0];
            uint4* dl = (uint4*)&Al[am][ak0];
            dh[0] = make_uint4(h[0], h[1], h[2], h[3]);
            dh[1] = make_uint4(h[4], h[5], h[6], h[7]);
            dl[0] = make_uint4(l[0], l[1], l[2], l[3]);
            dl[1] = make_uint4(l[4], l[5], l[6], l[7]);
        }
        {
            u32 h[8], l[8];
            #pragma unroll
            for (int j = 0; j < 8; j++)
                split2(breg[2*j], breg[2*j+1], h[j], l[j]);
            uint4* dh = (uint4*)&Bh[bn][bk0];
            uint4* dl = (uint4*)&Bl[bn][bk0];
            dh[0] = make_uint4(h[0], h[1], h[2], h[3]);
            dh[1] = make_uint4(h[4], h[5], h[6], h[7]);
            dl[0] = make_uint4(l[0], l[1], l[2], l[3]);
            dl[1] = make_uint4(l[4], l[5], l[6], l[7]);
        }
        __syncthreads();

        if (k0 + 32 < K) {
            #pragma unroll
            for (int j = 0; j < 4; j++)
                areg[j] = *(const float4*)(Xp + k0 + 32 + j * 4);
            #pragma unroll
            for (int j = 0; j < 16; j++)
                breg[j] = W[(size_t)(k0 + 32 + bk0 + j) * N + n0 + bn];
        }

        #pragma unroll
        for (int ks = 0; ks < 32; ks += 16) {
            u32 bh[4][2], bl[4][2];
            #pragma unroll
            for (int nf = 0; nf < 4; nf++) {
                int n = wn * 32 + nf * 8 + gid;
                bh[nf][0] = *(const u32*)&Bh[n][ks + tig * 2];
                bh[nf][1] = *(const u32*)&Bh[n][ks + 8 + tig * 2];
                bl[nf][0] = *(const u32*)&Bl[n][ks + tig * 2];
                bl[nf][1] = *(const u32*)&Bl[n][ks + 8 + tig * 2];
            }
            #pragma unroll
            for (int mf = 0; mf < 4; mf++) {
                int m = wm * 64 + mf * 16 + gid;
                u32 ah[4], al[4];
                ah[0] = *(const u32*)&Ah[m][ks + tig * 2];
                ah[1] = *(const u32*)&Ah[m + 8][ks + tig * 2];
                ah[2] = *(const u32*)&Ah[m][ks + 8 + tig * 2];
                ah[3] = *(const u32*)&Ah[m + 8][ks + 8 + tig * 2];
                al[0] = *(const u32*)&Al[m][ks + tig * 2];
                al[1] = *(const u32*)&Al[m + 8][ks + tig * 2];
                al[2] = *(const u32*)&Al[m][ks + 8 + tig * 2];
                al[3] = *(const u32*)&Al[m + 8][ks + 8 + tig * 2];
                #pragma unroll
                for (int nf = 0; nf < 4; nf++) {
                    mma16816(acc[mf][nf], ah, bh[nf]);
                    mma16816(acc[mf][nf], ah, bl[nf]);
                    mma16816(acc[mf][nf], al, bh[nf]);
                }
            }
        }
    }

    #pragma unroll
    for (int mf = 0; mf < 4; mf++) {
        int row = m0 + wm * 64 + mf * 16 + gid;
        #pragma unroll
        for (int nf = 0; nf < 4; nf++) {
            int col = n0 + wn * 32 + nf * 8 + tig * 2;
            float2 bb = *(const float2*)(bias + col);
            float2 v0, v1;
            v0.x = acc[mf][nf][0] + bb.x; v0.y = acc[mf][nf][1] + bb.y;
            v1.x = acc[mf][nf][2] + bb.x; v1.y = acc[mf][nf][3] + bb.y;
            *(float2*)(Y + (size_t)row * N + col) = v0;
            *(float2*)(Y + (size_t)(row + 8) * N + col) = v1;
        }
    }
}

// ---------------------------------------------------------------------------
// Flash attention on tensor cores, full split precision (Q,K,P,V hi/lo).
// Block = (128 q rows, head h, batch b); 8 warps x 16 rows; kv-tile 64.
// smem pitches: Q/K hd-major pitch 136 bf16; Vt kv-major pitch 72 bf16.
// Fragment bank pattern: word = 68*gid(+..)+tig -> 4*gid+tig mod 32, conflict-free.
// ---------------------------------------------------------------------------
#define FPITCH 136
#define VPITCH 72
#define SQ_SZ (128 * FPITCH)
#define SK_SZ (64 * FPITCH)
#define SV_SZ (128 * VPITCH)
#define FLASH2_SMEM_BYTES ((2 * SQ_SZ + 2 * SK_SZ + 2 * SV_SZ) * 2)

__global__ __launch_bounds__(256) void flash_mma_kernel(
    const float* __restrict__ Q,
    const __nv_bfloat16* __restrict__ Kbh, const __nv_bfloat16* __restrict__ Kbl,
    const __nv_bfloat16* __restrict__ Vth, const __nv_bfloat16* __restrict__ Vtl,
    float* __restrict__ A)
{
    extern __shared__ __align__(16) __nv_bfloat16 fsm[];
    __nv_bfloat16* sQh = fsm;
    __nv_bfloat16* sQl = fsm + SQ_SZ;
    __nv_bfloat16* sKh = fsm + 2 * SQ_SZ;
    __nv_bfloat16* sKl = fsm + 2 * SQ_SZ + SK_SZ;
    __nv_bfloat16* sVh = fsm + 2 * SQ_SZ + 2 * SK_SZ;
    __nv_bfloat16* sVl = fsm + 2 * SQ_SZ + 2 * SK_SZ + SV_SZ;

    const int tid  = threadIdx.x;
    const int lane = tid & 31;
    const int warp = tid >> 5;     // 0..7, rows warp*16 + gid, +8
    const int gid  = lane >> 2;
    const int tig  = lane & 3;
    const int q0   = blockIdx.x * 128;
    const int h    = blockIdx.y;
    const int b    = blockIdx.z;

    const float SCALE = 0.08838834764831843f;
    const float NEG   = -1e30f;

    // Convert Q tile (128 x 128) to hi/lo, once per block.
    {
        const float* Qb = Q + ((size_t)b * TQ_ + q0) * D_ + h * HD_;
        u32* wQh = (u32*)sQh;
        u32* wQl = (u32*)sQl;
        #pragma unroll
        for (int r = 0; r < 16; r++) {
            int f = tid + 256 * r;
            int row = f >> 5;
            int c4  = (f & 31) << 2;
            float4 v = *(const float4*)(Qb + (size_t)row * D_ + c4);
            u32 h0, l0, h1, l1;
            split2(v.x, v.y, h0, l0);
            split2(v.z, v.w, h1, l1);
            int wbase = row * 68 + (c4 >> 1);
            wQh[wbase] = h0; wQh[wbase + 1] = h1;
            wQl[wbase] = l0; wQl[wbase + 1] = l1;
        }
    }

    const __nv_bfloat16* Kh0 = Kbh + ((size_t)b * TKV_) * D_ + h * HD_;
    const __nv_bfloat16* Kl0 = Kbl + ((size_t)b * TKV_) * D_ + h * HD_;
    const __nv_bfloat16* Vh0 = Vth + ((size_t)b * D_ + h * HD_) * TKV_;
    const __nv_bfloat16* Vl0 = Vtl + ((size_t)b * D_ + h * HD_) * TKV_;
    const unsigned char* Mb  = g_M + ((size_t)b * TQ_ + q0) * TKV_;
    const unsigned char* M0  = Mb + (size_t)(warp * 16 + gid) * TKV_ + 2 * tig;
    const unsigned char* M1  = M0 + 8 * TKV_;

    float m0 = -INFINITY, m1 = -INFINITY, l0 = 0.0f, l1 = 0.0f;
    float o[16][4] = {};

    const u32* wQh = (const u32*)sQh;
    const u32* wQl = (const u32*)sQl;
    const u32* wKh = (const u32*)sKh;
    const u32* wKl = (const u32*)sKl;
    const u32* wVh = (const u32*)sVh;
    const u32* wVl = (const u32*)sVl;
    const int qr0 = (warp * 16 + gid) * 68;
    const int qr1 = qr0 + 8 * 68;

    for (int t = 0; t < TKV_ / 64; t++) {
        const int kv0 = t * 64;
        __syncthreads();   // previous PV done reading sK/sV

        // Load K tile (64 x 128 bf16, hi/lo)
        #pragma unroll
        for (int r = 0; r < 4; r++) {
            int f = tid + 256 * r;
            int row = f >> 4;
            int c8  = (f & 15) << 3;
            size_t g = (size_t)(kv0 + row) * D_ + c8;
            *(uint4*)(sKh + row * FPITCH + c8) = *(const uint4*)(Kh0 + g);
            *(uint4*)(sKl + row * FPITCH + c8) = *(const uint4*)(Kl0 + g);
        }
        // Load Vt tile (128 hd x 64 kv bf16, hi/lo)
        #pragma unroll
        for (int r = 0; r < 4; r++) {
            int f = tid + 256 * r;
            int hd = f >> 3;
            int c8 = (f & 7) << 3;
            size_t g = (size_t)hd * TKV_ + kv0 + c8;
            *(uint4*)(sVh + hd * VPITCH + c8) = *(const uint4*)(Vh0 + g);
            *(uint4*)(sVl + hd * VPITCH + c8) = *(const uint4*)(Vl0 + g);
        }
        __syncthreads();

        // S = Q @ K^T (split 3-product)
        float s[8][4] = {};
        #pragma unroll
        for (int ks = 0; ks < 8; ks++) {
            u32 ah[4], al[4];
            ah[0] = wQh[qr0 + 8 * ks + tig];
            ah[1] = wQh[qr1 + 8 * ks + tig];
            ah[2] = wQh[qr0 + 8 * ks + 4 + tig];
            ah[3] = wQh[qr1 + 8 * ks + 4 + tig];
            al[0] = wQl[qr0 + 8 * ks + tig];
            al[1] = wQl[qr1 + 8 * ks + tig];
            al[2] = wQl[qr0 + 8 * ks + 4 + tig];
            al[3] = wQl[qr1 + 8 * ks + 4 + tig];
            #pragma unroll
            for (int nf = 0; nf < 8; nf++) {
                int nw = (nf * 8 + gid) * 68 + 8 * ks + tig;
                u32 bh[2] = {wKh[nw], wKh[nw + 4]};
                u32 bl[2] = {wKl[nw], wKl[nw + 4]};
                mma16816(s[nf], ah, bh);
                mma16816(s[nf], ah, bl);
                mma16816(s[nf], al, bh);
            }
        }

        // Mask + scale
        float rm0 = -INFINITY, rm1 = -INFINITY;
        #pragma unroll
        for (int nf = 0; nf < 8; nf++) {
            uchar2 k0 = *(const uchar2*)(M0 + kv0 + nf * 8);
            uchar2 k1 = *(const uchar2*)(M1 + kv0 + nf * 8);
            s[nf][0] = k0.x ? s[nf][0] * SCALE : NEG;
            s[nf][1] = k0.y ? s[nf][1] * SCALE : NEG;
            s[nf][2] = k1.x ? s[nf][2] * SCALE : NEG;
            s[nf][3] = k1.y ? s[nf][3] * SCALE : NEG;
            rm0 = fmaxf(rm0, fmaxf(s[nf][0], s[nf][1]));
            rm1 = fmaxf(rm1, fmaxf(s[nf][2], s[nf][3]));
        }
        // Quad reduction (lanes gid*4+tig share a row)
        rm0 = fmaxf(rm0, __shfl_xor_sync(0xffffffffu, rm0, 1));
        rm0 = fmaxf(rm0, __shfl_xor_sync(0xffffffffu, rm0, 2));
        rm1 = fmaxf(rm1, __shfl_xor_sync(0xffffffffu, rm1, 1));
        rm1 = fmaxf(rm1, __shfl_xor_sync(0xffffffffu, rm1, 2));

        float mn0 = fmaxf(m0, rm0), mn1 = fmaxf(m1, rm1);
        float c0 = __expf(m0 - mn0), c1 = __expf(m1 - mn1);
        m0 = mn0; m1 = mn1;

        float rs0 = 0.0f, rs1 = 0.0f;
        u32 ph[8][2], pl[8][2];
        #pragma unroll
        for (int nf = 0; nf < 8; nf++) {
            float p0 = __expf(s[nf][0] - m0);
            float p1 = __expf(s[nf][1] - m0);
            float p2 = __expf(s[nf][2] - m1);
            float p3 = __expf(s[nf][3] - m1);
            rs0 += p0 + p1;
            rs1 += p2 + p3;
            split2(p0, p1, ph[nf][0], pl[nf][0]);
            split2(p2, p3, ph[nf][1], pl[nf][1]);
        }
        rs0 += __shfl_xor_sync(0xffffffffu, rs0, 1);
        rs0 += __shfl_xor_sync(0xffffffffu, rs0, 2);
        rs1 += __shfl_xor_sync(0xffffffffu, rs1, 1);
        rs1 += __shfl_xor_sync(0xffffffffu, rs1, 2);
        l0 = l0 * c0 + rs0;
        l1 = l1 * c1 + rs1;
        #pragma unroll
        for (int nf2 = 0; nf2 < 16; nf2++) {
            o[nf2][0] *= c0; o[nf2][1] *= c0;
            o[nf2][2] *= c1; o[nf2][3] *= c1;
        }

        // O += P @ V (split 3-product); P frags re-fed as A operands.
        #pragma unroll
        for (int jp = 0; jp < 4; jp++) {
            u32 ah[4] = {ph[2*jp][0], ph[2*jp][1], ph[2*jp+1][0], ph[2*jp+1][1]};
            u32 al[4] = {pl[2*jp][0], pl[2*jp][1], pl[2*jp+1][0], pl[2*jp+1][1]};
            #pragma unroll
            for (int nf2 = 0; nf2 < 16; nf2++) {
                int nw = (nf2 * 8 + gid) * 36 + 8 * jp + tig;
                u32 bh[2] = {wVh[nw], wVh[nw + 4]};
                u32 bl[2] = {wVl[nw], wVl[nw + 4]};
                mma16816(o[nf2], ah, bh);
                mma16816(o[nf2], ah, bl);
                mma16816(o[nf2], al, bh);
            }
        }
    }

    // Epilogue: normalize; wipe fully-masked rows.
    float inv0 = (m0 < -1e29f) ? 0.0f : (1.0f / l0);
    float inv1 = (m1 < -1e29f) ? 0.0f : (1.0f / l1);
    int r0 = q0 + warp * 16 + gid;
    float* out0 = A + ((size_t)b * TQ_ + r0) * D_ + h * HD_;
    float* out1 = out0 + (size_t)8 * D_;
    #pragma unroll
    for (int nf2 = 0; nf2 < 16; nf2++) {
        int col = nf2 * 8 + 2 * tig;
        float2 v0 = {o[nf2][0] * inv0, o[nf2][1] * inv0};
        float2 v1 = {o[nf2][2] * inv1, o[nf2][3] * inv1};
        *(float2*)(out0 + col) = v0;
        *(float2*)(out1 + col) = v1;
    }
}

// ---------------------------------------------------------------------------
// Launch
// ---------------------------------------------------------------------------
extern "C" void kernel_launch(void* const* d_in, const int* in_sizes, int n_in,
                              void* d_out, int out_size)
{
    const float* xq   = (const float*)d_in[0];
    const float* xkv  = (const float*)d_in[1];
    const void*  mask = d_in[2];
    const float* Wq = (const float*)d_in[3];
    const float* bq = (const float*)d_in[4];
    const float* Wk = (const float*)d_in[5];
    const float* bk = (const float*)d_in[6];
    const float* Wv = (const float*)d_in[7];
    const float* bv = (const float*)d_in[8];
    const float* Wo = (const float*)d_in[9];
    const float* bo = (const float*)d_in[10];

    float *gQ, *gK, *gV, *gA;
    __nv_bfloat16 *gKbh, *gKbl, *gVth, *gVtl;
    cudaGetSymbolAddress((void**)&gQ, g_Q);
    cudaGetSymbolAddress((void**)&gK, g_K);
    cudaGetSymbolAddress((void**)&gV, g_V);
    cudaGetSymbolAddress((void**)&gA, g_A);
    cudaGetSymbolAddress((void**)&gKbh, g_Kbh);
    cudaGetSymbolAddress((void**)&gKbl, g_Kbl);
    cudaGetSymbolAddress((void**)&gVth, g_Vth);
    cudaGetSymbolAddress((void**)&gVtl, g_Vtl);

    const int Mq = B_ * TQ_;    // 2048
    const int Mkv = B_ * TKV_;  // 16384

    // Mask normalization
    detect_mask_kernel<<<1, 256>>>((const unsigned char*)mask);
    convert_mask_kernel<<<(B_ * TQ_ * TKV_) / (256 * 4), 256>>>(mask);

    // Projections (tensor cores, bf16 split; validated R11)
    gemm_mma_kernel<<<dim3(D_ / 128, Mq / 128), 256>>>(xq, Wq, bq, gQ, Mq, D_, D_);
    gemm_mma_kernel<<<dim3(D_ / 128, Mkv / 128), 256>>>(xkv, Wk, bk, gK, Mkv, D_, D_);
    gemm_mma_kernel<<<dim3(D_ / 128, Mkv / 128), 256>>>(xkv, Wv, bv, gV, Mkv, D_, D_);

    // Prepack K (split) and V (transpose + split) for the flash kernel
    pack_split_kernel<<<(B_ * TKV_ * D_) / (256 * 4), 256>>>(gK, gKbh, gKbl);
    transpose_split_kernel<<<dim3(TKV_ / 64, D_ / 64, B_), 256>>>(gV, gVth, gVtl);

    // Attention on tensor cores
    cudaFuncSetAttribute(flash_mma_kernel, cudaFuncAttributeMaxDynamicSharedMemorySize,
                         FLASH2_SMEM_BYTES);
    flash_mma_kernel<<<dim3(TQ_ / 128, H_, B_), 256, FLASH2_SMEM_BYTES>>>(
        gQ, gKbh, gKbl, gVth, gVtl, gA);

    // Output projection
    gemm_mma_kernel<<<dim3(D_ / 128, Mq / 128), 256>>>(gA, Wo, bo, (float*)d_out,
                                                       Mq, D_, D_);
}